// round 8
// baseline (speedup 1.0000x reference)
#include <cuda_runtime.h>
#include <cuda_bf16.h>

// Problem constants
#define NB     64
#define ADJ    1000
#define NN     (NB*ADJ)        // 64000 nodes
#define NE     (1<<20)         // edges
#define MM     32000           // selected pairs
#define DD     128             // feature dim
#define PAD    64              // padded CSR row slots (P(deg>=64) ~ 1e-18)

// ---------------- scratch (device globals; 16B-aligned) ----------------------
__device__ __align__(16) float g_agg1 [NN*DD];     // A @ x1
__device__ __align__(16) float g_t2   [NN*DD];     // A @ (A @ x1) (masked rows)
__device__ __align__(16) float g_Wc  [DD*DD];
__device__ __align__(16) float g_Wall[DD*DD];
__device__ __align__(16) float g_c0  [DD];
__device__ __align__(16) float g_c1  [DD];
__device__ __align__(16) int   g_esrc[NN*PAD];     // padded CSR: 16 MB
__device__ __align__(16) int   g_cnt [NN];         // indegree (true count)
__device__ __align__(16) int   g_need[NN];         // node needed by sel1?
__device__ int g_is64;

// ---------------- index helpers ---------------------------------------------
__device__ __forceinline__ long long load_idx(const void* p, long long i, int is64) {
    return is64 ? ((const long long*)p)[i] : (long long)((const int*)p)[i];
}
__device__ __forceinline__ long long clampll(long long v, long long lo, long long hi) {
    return v < lo ? lo : (v > hi ? hi : v);
}

// ---------------- dtype detect + zero int scratch ----------------------------
__global__ void detect_zero_kernel(const unsigned int* __restrict__ e) {
    int i = blockIdx.x * blockDim.x + threadIdx.x;
    if (i == 0) {
        int ok = 1;
        #pragma unroll
        for (int q = 1; q < 64; q += 2) if (e[q] != 0u) ok = 0;
        g_is64 = ok;
    }
    if (i < NN) { g_cnt[i] = 0; g_need[i] = 0; }
}

// ---------------- mark nodes needed by branch-1 selection --------------------
__global__ void need_kernel(const void* __restrict__ bi, const void* __restrict__ ni) {
    int m = blockIdx.x * blockDim.x + threadIdx.x;
    if (m >= MM) return;
    int is64 = g_is64;
    long long b = clampll(load_idx(bi, m, is64), 0, NB  - 1);
    long long n = clampll(load_idx(ni, m, is64), 0, ADJ - 1);
    g_need[(int)(b * ADJ + n)] = 1;
}

// ---------------- padded-CSR fill (single pass, no scan) ---------------------
__global__ __launch_bounds__(256) void fill_kernel(const void* __restrict__ ei) {
    int e = blockIdx.x * blockDim.x + threadIdx.x;
    if (e >= NE) return;
    int is64 = g_is64;
    int src = (int)clampll(load_idx(ei, e,                 is64), 0, NN - 1);
    int dst = (int)clampll(load_idx(ei, (long long)NE + e, is64), 0, NN - 1);
    int pos = atomicAdd(&g_cnt[dst], 1);
    if (pos < PAD) g_esrc[dst * PAD + pos] = src;
}

// ---------------- aggregation: warp/node, float4 lanes, predicated 8-MLP -----
__global__ __launch_bounds__(256) void agg_kernel(
    const float* __restrict__ X, float* __restrict__ out, int use_mask)
{
    int w    = threadIdx.x >> 5;
    int lane = threadIdx.x & 31;
    int n    = blockIdx.x * 8 + w;
    if (n >= NN) return;
    if (use_mask && !g_need[n]) return;

    int s0 = n * PAD;
    int cn = min(g_cnt[n], PAD);
    const float4* __restrict__ Xv = (const float4*)X;

    float4 acc = make_float4(0.f, 0.f, 0.f, 0.f);
    for (int k = 0; k < cn; k += 8) {
        int   idx[8];
        float msk[8];
        #pragma unroll
        for (int u = 0; u < 8; u++) {
            int kk   = k + u;
            int safe = kk < cn ? kk : cn - 1;
            msk[u]   = kk < cn ? 1.f : 0.f;
            idx[u]   = __ldg(&g_esrc[s0 + safe]);
        }
        float4 v[8];
        #pragma unroll
        for (int u = 0; u < 8; u++) v[u] = __ldg(Xv + (long long)idx[u] * 32 + lane);
        #pragma unroll
        for (int u = 0; u < 8; u++) {
            acc.x = fmaf(msk[u], v[u].x, acc.x);
            acc.y = fmaf(msk[u], v[u].y, acc.y);
            acc.z = fmaf(msk[u], v[u].z, acc.z);
            acc.w = fmaf(msk[u], v[u].w, acc.w);
        }
    }
    ((float4*)out)[(long long)n * 32 + lane] = acc;
}

// ---------------- 128x128 weight folds (hidden on side stream) ---------------
__global__ void matmul128(const float* __restrict__ A, const float* __restrict__ B,
                          const float* __restrict__ avec, const float* __restrict__ addv,
                          float* __restrict__ C, float* __restrict__ cvec) {
    int j = threadIdx.x;
    int i = blockIdx.x;
    if (i < DD) {
        float acc = 0.f;
        #pragma unroll 16
        for (int k = 0; k < DD; k++) acc += __ldg(&A[i*DD + k]) * __ldg(&B[k*DD + j]);
        C[i*DD + j] = acc;
    } else {
        float acc = addv ? __ldg(&addv[j]) : 0.f;
        #pragma unroll 16
        for (int k = 0; k < DD; k++) acc += __ldg(&avec[k]) * __ldg(&B[k*DD + j]);
        cvec[j] = acc;
    }
}

// ---------------- gather rows + GEMM, 4x8 register blocking ------------------
__global__ __launch_bounds__(256) void gather_mm(
    const float* __restrict__ X, const void* __restrict__ bi,
    const void* __restrict__ ni,
    const float* __restrict__ W, const float* __restrict__ bias,
    int use_deg, const float* __restrict__ c1,
    float* __restrict__ out)
{
    __shared__ __align__(16) float sW [32 * DD];   // 16 KB
    __shared__ __align__(16) float sXT[32 * 68];   // 8.5 KB, pad 68
    __shared__ int sIdx[64];

    int t  = threadIdx.x;
    int m0 = blockIdx.x * 64;
    if (t < 64) {
        int is64 = g_is64;
        long long b = clampll(load_idx(bi, m0 + t, is64), 0, NB  - 1);
        long long n = clampll(load_idx(ni, m0 + t, is64), 0, ADJ - 1);
        sIdx[t] = (int)(b * ADJ + n);
    }
    __syncthreads();

    int rg = t >> 4;
    int cg = t & 15;
    float acc[4][8];
    #pragma unroll
    for (int i = 0; i < 4; i++)
        #pragma unroll
        for (int j = 0; j < 8; j++) acc[i][j] = 0.f;

    for (int kc = 0; kc < DD; kc += 32) {
        __syncthreads();
        #pragma unroll
        for (int i = 0; i < 4; i++) {
            int off = i * 256 + t;
            ((float4*)sW)[off] = __ldg(((const float4*)(W + kc * DD)) + off);
        }
        #pragma unroll
        for (int i = 0; i < 2; i++) {
            int u = i * 256 + t;
            int r = u >> 3;
            int c = u & 7;
            float4 v = __ldg(((const float4*)(X + (long long)sIdx[r] * DD + kc)) + c);
            sXT[(c*4+0) * 68 + r] = v.x;
            sXT[(c*4+1) * 68 + r] = v.y;
            sXT[(c*4+2) * 68 + r] = v.z;
            sXT[(c*4+3) * 68 + r] = v.w;
        }
        __syncthreads();
        #pragma unroll
        for (int k = 0; k < 32; k++) {
            float4 xv = *(const float4*)(sXT + k * 68 + rg * 4);
            float4 wa = *(const float4*)(sW + k * DD + cg * 8);
            float4 wb = *(const float4*)(sW + k * DD + cg * 8 + 4);
            float xr[4] = {xv.x, xv.y, xv.z, xv.w};
            float wr[8] = {wa.x, wa.y, wa.z, wa.w, wb.x, wb.y, wb.z, wb.w};
            #pragma unroll
            for (int i = 0; i < 4; i++)
                #pragma unroll
                for (int j = 0; j < 8; j++) acc[i][j] += xr[i] * wr[j];
        }
    }

    float bv[8], cv[8];
    #pragma unroll
    for (int j = 0; j < 8; j++) {
        bv[j] = __ldg(&bias[cg*8 + j]);
        cv[j] = use_deg ? __ldg(&c1[cg*8 + j]) : 0.f;
    }
    #pragma unroll
    for (int i = 0; i < 4; i++) {
        int row = rg * 4 + i;
        float dscale = use_deg ? (float)g_cnt[sIdx[row]] : 0.f;
        float* orow = out + (long long)(m0 + row) * DD + cg * 8;
        float4 o0, o1;
        o0.x = acc[i][0] + bv[0] + dscale * cv[0];
        o0.y = acc[i][1] + bv[1] + dscale * cv[1];
        o0.z = acc[i][2] + bv[2] + dscale * cv[2];
        o0.w = acc[i][3] + bv[3] + dscale * cv[3];
        o1.x = acc[i][4] + bv[4] + dscale * cv[4];
        o1.y = acc[i][5] + bv[5] + dscale * cv[5];
        o1.z = acc[i][6] + bv[6] + dscale * cv[6];
        o1.w = acc[i][7] + bv[7] + dscale * cv[7];
        *((float4*)orow)       = o0;
        *((float4*)(orow + 4)) = o1;
    }
}

// ---------------- launch -----------------------------------------------------
extern "C" void kernel_launch(void* const* d_in, const int* in_sizes, int n_in,
                              void* d_out, int out_size)
{
    const float* x0  = (const float*)d_in[0];
    const float* x1  = (const float*)d_in[1];
    const void*  ei  = d_in[2];
    const void*  b0  = d_in[3];
    const void*  n0  = d_in[4];
    const void*  b1i = d_in[5];
    const void*  n1i = d_in[6];
    const float* W1  = (const float*)d_in[7];
    const float* b1  = (const float*)d_in[8];
    const float* W2  = (const float*)d_in[9];
    const float* b2  = (const float*)d_in[10];
    const float* Wl  = (const float*)d_in[11];
    const float* bl  = (const float*)d_in[12];
    const float* Wfi = (const float*)d_in[13];
    const float* bfi = (const float*)d_in[14];
    float* out = (float*)d_out;

    float *agg1, *t2, *Wc, *Wall, *c0, *c1;
    cudaGetSymbolAddress((void**)&agg1, g_agg1);
    cudaGetSymbolAddress((void**)&t2,   g_t2);
    cudaGetSymbolAddress((void**)&Wc,   g_Wc);
    cudaGetSymbolAddress((void**)&Wall, g_Wall);
    cudaGetSymbolAddress((void**)&c0,   g_c0);
    cudaGetSymbolAddress((void**)&c1,   g_c1);

    static cudaStream_t s2 = nullptr;
    static cudaEvent_t  eA = nullptr, eB = nullptr;
    if (s2 == nullptr) {
        cudaStreamCreateWithFlags(&s2, cudaStreamNonBlocking);
        cudaEventCreateWithFlags(&eA, cudaEventDisableTiming);
        cudaEventCreateWithFlags(&eB, cudaEventDisableTiming);
    }

    // launch-call #0 main: detect + zero
    detect_zero_kernel<<<(NN + 255) / 256, 256>>>((const unsigned int*)ei);
    cudaEventRecord(eA, 0);

    // side stream issued FIRST so gather_mm lands at launch-call index 3
    // (ncu -s5 -c1 profiles call #3 -> gather_mm profile next round)
    cudaStreamWaitEvent(s2, eA, 0);
    matmul128<<<DD + 1, DD, 0, s2>>>(W2, Wl, b2, bl,      Wc,   c0);   // #1
    matmul128<<<DD + 1, DD, 0, s2>>>(W1, Wc, b1, nullptr, Wall, c1);   // #2
    gather_mm<<<MM / 64, 256, 0, s2>>>(x0, b0, n0, Wfi, bfi, 0, nullptr, out); // #3
    need_kernel<<<(MM + 255) / 256, 256, 0, s2>>>(b1i, n1i);           // #4
    cudaEventRecord(eB, s2);

    // main stream: CSR fill + aggregation pass 1
    fill_kernel<<<NE / 256, 256>>>(ei);                                // #5
    agg_kernel<<<(NN + 7) / 8, 256>>>(x1, agg1, 0);                    // #6

    // join: agg2 needs g_need; gather_mm1 needs Wall/c0/c1
    cudaStreamWaitEvent(0, eB, 0);
    agg_kernel<<<(NN + 7) / 8, 256>>>(agg1, t2, 1);                    // #7
    gather_mm<<<MM / 64, 256>>>(t2, b1i, n1i, Wall, c0, 1, c1, out + (long long)MM * DD); // #8
}

// round 9
// speedup vs baseline: 1.0181x; 1.0181x over previous
#include <cuda_runtime.h>
#include <cuda_bf16.h>

// Problem constants
#define NB     64
#define ADJ    1000
#define NN     (NB*ADJ)        // 64000 nodes
#define NE     (1<<20)         // edges
#define MM     32000           // selected pairs
#define DD     128             // feature dim
#define PAD    64              // padded CSR row slots (P(deg>=64) ~ 1e-18)

// ---------------- scratch (device globals; 16B-aligned) ----------------------
__device__ __align__(16) float g_agg1 [NN*DD];     // A @ x1
__device__ __align__(16) float g_t2   [NN*DD];     // A @ (A @ x1) (masked rows)
__device__ __align__(16) float g_Wc  [DD*DD];
__device__ __align__(16) float g_Wall[DD*DD];
__device__ __align__(16) float g_c0  [DD];
__device__ __align__(16) float g_c1  [DD];
__device__ __align__(16) int   g_esrc[NN*PAD];     // padded CSR: 16 MB
__device__ __align__(16) int   g_cnt [NN];         // indegree (true count)
__device__ __align__(16) int   g_need[NN];         // node needed by sel1?
__device__ int g_is64;

// ---------------- index helpers ---------------------------------------------
__device__ __forceinline__ long long load_idx(const void* p, long long i, int is64) {
    return is64 ? ((const long long*)p)[i] : (long long)((const int*)p)[i];
}
__device__ __forceinline__ long long clampll(long long v, long long lo, long long hi) {
    return v < lo ? lo : (v > hi ? hi : v);
}

// ---------------- dtype detect + zero int scratch ----------------------------
__global__ void detect_zero_kernel(const unsigned int* __restrict__ e) {
    int i = blockIdx.x * blockDim.x + threadIdx.x;
    if (i == 0) {
        int ok = 1;
        #pragma unroll
        for (int q = 1; q < 64; q += 2) if (e[q] != 0u) ok = 0;
        g_is64 = ok;
    }
    if (i < NN) { g_cnt[i] = 0; g_need[i] = 0; }
}

// ---------------- mark nodes needed by branch-1 selection --------------------
__global__ void need_kernel(const void* __restrict__ bi, const void* __restrict__ ni) {
    int m = blockIdx.x * blockDim.x + threadIdx.x;
    if (m >= MM) return;
    int is64 = g_is64;
    long long b = clampll(load_idx(bi, m, is64), 0, NB  - 1);
    long long n = clampll(load_idx(ni, m, is64), 0, ADJ - 1);
    g_need[(int)(b * ADJ + n)] = 1;
}

// ---------------- padded-CSR fill (single pass, no scan) ---------------------
__global__ __launch_bounds__(256) void fill_kernel(const void* __restrict__ ei) {
    int e = blockIdx.x * blockDim.x + threadIdx.x;
    if (e >= NE) return;
    int is64 = g_is64;
    int src = (int)clampll(load_idx(ei, e,                 is64), 0, NN - 1);
    int dst = (int)clampll(load_idx(ei, (long long)NE + e, is64), 0, NN - 1);
    int pos = atomicAdd(&g_cnt[dst], 1);
    if (pos < PAD) g_esrc[dst * PAD + pos] = src;
}

// ---------------- aggregation: warp/node, float4 lanes, 8-deep MLP -----------
__global__ __launch_bounds__(256) void agg_kernel(
    const float* __restrict__ X, float* __restrict__ out, int use_mask)
{
    int w    = threadIdx.x >> 5;
    int lane = threadIdx.x & 31;
    int n    = blockIdx.x * 8 + w;
    if (n >= NN) return;
    if (use_mask && !g_need[n]) return;

    int s0 = n * PAD;
    int cn = min(g_cnt[n], PAD);
    const float4* __restrict__ Xv = (const float4*)X;

    float4 acc = make_float4(0.f, 0.f, 0.f, 0.f);
    int k = 0;
    for (; k + 8 <= cn; k += 8) {
        int idx[8];
        #pragma unroll
        for (int u = 0; u < 8; u++) idx[u] = __ldg(&g_esrc[s0 + k + u]);
        float4 v[8];
        #pragma unroll
        for (int u = 0; u < 8; u++) v[u] = __ldg(Xv + (long long)idx[u] * 32 + lane);
        float4 s0v, s1v, s2v, s3v, t0, t1, r;
        s0v.x=v[0].x+v[1].x; s0v.y=v[0].y+v[1].y; s0v.z=v[0].z+v[1].z; s0v.w=v[0].w+v[1].w;
        s1v.x=v[2].x+v[3].x; s1v.y=v[2].y+v[3].y; s1v.z=v[2].z+v[3].z; s1v.w=v[2].w+v[3].w;
        s2v.x=v[4].x+v[5].x; s2v.y=v[4].y+v[5].y; s2v.z=v[4].z+v[5].z; s2v.w=v[4].w+v[5].w;
        s3v.x=v[6].x+v[7].x; s3v.y=v[6].y+v[7].y; s3v.z=v[6].z+v[7].z; s3v.w=v[6].w+v[7].w;
        t0.x=s0v.x+s1v.x; t0.y=s0v.y+s1v.y; t0.z=s0v.z+s1v.z; t0.w=s0v.w+s1v.w;
        t1.x=s2v.x+s3v.x; t1.y=s2v.y+s3v.y; t1.z=s2v.z+s3v.z; t1.w=s2v.w+s3v.w;
        r.x=t0.x+t1.x; r.y=t0.y+t1.y; r.z=t0.z+t1.z; r.w=t0.w+t1.w;
        acc.x+=r.x; acc.y+=r.y; acc.z+=r.z; acc.w+=r.w;
    }
    for (; k < cn; k++) {
        int i0 = __ldg(&g_esrc[s0 + k]);
        float4 a = __ldg(Xv + (long long)i0 * 32 + lane);
        acc.x += a.x; acc.y += a.y; acc.z += a.z; acc.w += a.w;
    }
    ((float4*)out)[(long long)n * 32 + lane] = acc;
}

// ---------------- 128x128 weight folds, coalesced B via smem -----------------
// 129 blocks x 128 threads. Block i<128: C[i][:] = A[i][:] @ B. Block 128:
// cvec = avec @ B (+ addv). B chunks of 16 rows staged in smem (coalesced).
__global__ __launch_bounds__(128) void matmul128(
    const float* __restrict__ A, const float* __restrict__ B,
    const float* __restrict__ avec, const float* __restrict__ addv,
    float* __restrict__ C, float* __restrict__ cvec)
{
    __shared__ __align__(16) float sB[16 * DD];   // 8 KB
    int j = threadIdx.x;
    int i = blockIdx.x;
    const float* arow = (i < DD) ? (A + i * DD) : avec;

    float acc = 0.f;
    for (int kc = 0; kc < DD; kc += 16) {
        __syncthreads();
        // 16 rows x 128 cols = 512 float4; 4 per thread, coalesced
        #pragma unroll
        for (int u = 0; u < 4; u++) {
            int off = u * 128 + j;
            ((float4*)sB)[off] = __ldg(((const float4*)(B + kc * DD)) + off);
        }
        __syncthreads();
        #pragma unroll
        for (int k = 0; k < 16; k++)
            acc = fmaf(__ldg(&arow[kc + k]), sB[k * DD + j], acc);
    }
    if (i < DD) C[i * DD + j] = acc;
    else        cvec[j] = acc + (addv ? __ldg(&addv[j]) : 0.f);
}

// ---------------- gather rows + GEMM, 4x8 tile, conflict-free smem -----------
// 64 rows/block, 256 threads. Full 512B X rows gathered ONCE into sX[64][129]
// (conflict-free scalar stores, broadcast reads). W staged in 16-row chunks.
__global__ __launch_bounds__(256) void gather_mm(
    const float* __restrict__ X, const void* __restrict__ bi,
    const void* __restrict__ ni,
    const float* __restrict__ W, const float* __restrict__ bias,
    int use_deg, const float* __restrict__ c1,
    float* __restrict__ out)
{
    __shared__ __align__(16) float sX[64 * 129];   // 33 KB, pad 129
    __shared__ __align__(16) float sW[16 * DD];    // 8 KB
    __shared__ int sIdx[64];

    int t  = threadIdx.x;
    int m0 = blockIdx.x * 64;
    if (t < 64) {
        int is64 = g_is64;
        long long b = clampll(load_idx(bi, m0 + t, is64), 0, NB  - 1);
        long long n = clampll(load_idx(ni, m0 + t, is64), 0, ADJ - 1);
        sIdx[t] = (int)(b * ADJ + n);
    }
    __syncthreads();

    // gather full rows once: 64 rows x 32 float4 = 2048 float4, 8 per thread.
    // thread u = i*256+t -> row r = u>>5, float4 c = u&31.
    // scalar-store banks (129r + 4c + u)%32 = (r + 4c + u)%32: conflict-free.
    #pragma unroll
    for (int i = 0; i < 8; i++) {
        int u = i * 256 + t;
        int r = u >> 5;
        int c = u & 31;
        float4 v = __ldg(((const float4*)(X + (long long)sIdx[r] * DD)) + c);
        float* dstp = sX + r * 129 + c * 4;
        dstp[0] = v.x; dstp[1] = v.y; dstp[2] = v.z; dstp[3] = v.w;
    }

    int rg = t >> 4;          // 0..15 -> rows rg*4..+3
    int cg = t & 15;          // 0..15 -> cols cg*8..+7
    float acc[4][8];
    #pragma unroll
    for (int i = 0; i < 4; i++)
        #pragma unroll
        for (int j = 0; j < 8; j++) acc[i][j] = 0.f;

    for (int kc = 0; kc < DD; kc += 16) {
        __syncthreads();
        // W chunk: 16 rows x 128 = 512 float4, 2 per thread, coalesced
        #pragma unroll
        for (int i = 0; i < 2; i++) {
            int off = i * 256 + t;
            ((float4*)sW)[off] = __ldg(((const float4*)(W + kc * DD)) + off);
        }
        __syncthreads();
        #pragma unroll
        for (int k = 0; k < 16; k++) {
            // x reads: 16 threads (same rg) broadcast each address
            float xr[4];
            #pragma unroll
            for (int i = 0; i < 4; i++) xr[i] = sX[(rg * 4 + i) * 129 + kc + k];
            float4 wa = *(const float4*)(sW + k * DD + cg * 8);
            float4 wb = *(const float4*)(sW + k * DD + cg * 8 + 4);
            float wr[8] = {wa.x, wa.y, wa.z, wa.w, wb.x, wb.y, wb.z, wb.w};
            #pragma unroll
            for (int i = 0; i < 4; i++)
                #pragma unroll
                for (int j = 0; j < 8; j++) acc[i][j] = fmaf(xr[i], wr[j], acc[i][j]);
        }
    }

    float bv[8], cv[8];
    #pragma unroll
    for (int j = 0; j < 8; j++) {
        bv[j] = __ldg(&bias[cg*8 + j]);
        cv[j] = use_deg ? __ldg(&c1[cg*8 + j]) : 0.f;
    }
    #pragma unroll
    for (int i = 0; i < 4; i++) {
        int row = rg * 4 + i;
        float dscale = use_deg ? (float)g_cnt[sIdx[row]] : 0.f;
        float* orow = out + (long long)(m0 + row) * DD + cg * 8;
        float4 o0, o1;
        o0.x = acc[i][0] + bv[0] + dscale * cv[0];
        o0.y = acc[i][1] + bv[1] + dscale * cv[1];
        o0.z = acc[i][2] + bv[2] + dscale * cv[2];
        o0.w = acc[i][3] + bv[3] + dscale * cv[3];
        o1.x = acc[i][4] + bv[4] + dscale * cv[4];
        o1.y = acc[i][5] + bv[5] + dscale * cv[5];
        o1.z = acc[i][6] + bv[6] + dscale * cv[6];
        o1.w = acc[i][7] + bv[7] + dscale * cv[7];
        *((float4*)orow)       = o0;
        *((float4*)(orow + 4)) = o1;
    }
}

// ---------------- launch -----------------------------------------------------
extern "C" void kernel_launch(void* const* d_in, const int* in_sizes, int n_in,
                              void* d_out, int out_size)
{
    const float* x0  = (const float*)d_in[0];
    const float* x1  = (const float*)d_in[1];
    const void*  ei  = d_in[2];
    const void*  b0  = d_in[3];
    const void*  n0  = d_in[4];
    const void*  b1i = d_in[5];
    const void*  n1i = d_in[6];
    const float* W1  = (const float*)d_in[7];
    const float* b1  = (const float*)d_in[8];
    const float* W2  = (const float*)d_in[9];
    const float* b2  = (const float*)d_in[10];
    const float* Wl  = (const float*)d_in[11];
    const float* bl  = (const float*)d_in[12];
    const float* Wfi = (const float*)d_in[13];
    const float* bfi = (const float*)d_in[14];
    float* out = (float*)d_out;

    float *agg1, *t2, *Wc, *Wall, *c0, *c1;
    cudaGetSymbolAddress((void**)&agg1, g_agg1);
    cudaGetSymbolAddress((void**)&t2,   g_t2);
    cudaGetSymbolAddress((void**)&Wc,   g_Wc);
    cudaGetSymbolAddress((void**)&Wall, g_Wall);
    cudaGetSymbolAddress((void**)&c0,   g_c0);
    cudaGetSymbolAddress((void**)&c1,   g_c1);

    static cudaStream_t s2 = nullptr;
    static cudaEvent_t  eA = nullptr, eB = nullptr;
    if (s2 == nullptr) {
        cudaStreamCreateWithFlags(&s2, cudaStreamNonBlocking);
        cudaEventCreateWithFlags(&eA, cudaEventDisableTiming);
        cudaEventCreateWithFlags(&eB, cudaEventDisableTiming);
    }

    // launch-call #0 main: detect + zero
    detect_zero_kernel<<<(NN + 255) / 256, 256>>>((const unsigned int*)ei);
    cudaEventRecord(eA, 0);

    // side stream (gather_mm stays at launch-call index 3 for ncu verification)
    cudaStreamWaitEvent(s2, eA, 0);
    matmul128<<<DD + 1, DD, 0, s2>>>(W2, Wl, b2, bl,      Wc,   c0);   // #1
    matmul128<<<DD + 1, DD, 0, s2>>>(W1, Wc, b1, nullptr, Wall, c1);   // #2
    gather_mm<<<MM / 64, 256, 0, s2>>>(x0, b0, n0, Wfi, bfi, 0, nullptr, out); // #3
    need_kernel<<<(MM + 255) / 256, 256, 0, s2>>>(b1i, n1i);           // #4
    cudaEventRecord(eB, s2);

    // main stream: CSR fill + aggregation pass 1
    fill_kernel<<<NE / 256, 256>>>(ei);                                // #5
    agg_kernel<<<(NN + 7) / 8, 256>>>(x1, agg1, 0);                    // #6

    // join: agg2 needs g_need; gather_mm1 needs Wall/c0/c1
    cudaStreamWaitEvent(0, eB, 0);
    agg_kernel<<<(NN + 7) / 8, 256>>>(agg1, t2, 1);                    // #7
    gather_mm<<<MM / 64, 256>>>(t2, b1i, n1i, Wall, c0, 1, c1, out + (long long)MM * DD); // #8
}

// round 10
// speedup vs baseline: 1.4129x; 1.3878x over previous
#include <cuda_runtime.h>
#include <cuda_bf16.h>

// Problem constants
#define NB     64
#define ADJ    1000
#define NN     (NB*ADJ)        // 64000 nodes
#define NE     (1<<20)         // edges
#define MM     32000           // selected pairs
#define DD     128             // feature dim
#define PAD    64              // padded CSR row slots

// ---------------- scratch ----------------------------------------------------
__device__ __align__(16) float g_agg1 [NN*DD];
__device__ __align__(16) float g_t2   [NN*DD];
__device__ __align__(16) float g_Wc    [DD*DD];
__device__ __align__(16) float g_Wall  [DD*DD];
__device__ __align__(16) float g_Wfi_h [DD*DD];
__device__ __align__(16) float g_Wfi_l [DD*DD];
__device__ __align__(16) float g_Wall_h[DD*DD];
__device__ __align__(16) float g_Wall_l[DD*DD];
__device__ __align__(16) float g_c0  [DD];
__device__ __align__(16) float g_c1  [DD];
__device__ __align__(16) int   g_esrc[NN*PAD];
__device__ __align__(16) int   g_cnt [NN];
__device__ __align__(16) int   g_need[NN];
__device__ int g_is64;

// ---------------- helpers ----------------------------------------------------
__device__ __forceinline__ long long load_idx(const void* p, long long i, int is64) {
    return is64 ? ((const long long*)p)[i] : (long long)((const int*)p)[i];
}
__device__ __forceinline__ long long clampll(long long v, long long lo, long long hi) {
    return v < lo ? lo : (v > hi ? hi : v);
}
__device__ __forceinline__ unsigned tf32_of(float x) {
    unsigned r; asm("cvt.rna.tf32.f32 %0, %1;" : "=r"(r) : "f"(x)); return r;
}
__device__ __forceinline__ void mma_tf32(
    float& c0, float& c1, float& c2, float& c3,
    unsigned a0, unsigned a1, unsigned a2, unsigned a3,
    unsigned b0, unsigned b1)
{
    asm volatile(
        "mma.sync.aligned.m16n8k8.row.col.f32.tf32.tf32.f32 "
        "{%0,%1,%2,%3}, {%4,%5,%6,%7}, {%8,%9}, {%0,%1,%2,%3};"
        : "+f"(c0), "+f"(c1), "+f"(c2), "+f"(c3)
        : "r"(a0), "r"(a1), "r"(a2), "r"(a3), "r"(b0), "r"(b1));
}

// ---------------- dtype detect + zero int scratch ----------------------------
__global__ void detect_zero_kernel(const unsigned int* __restrict__ e) {
    int i = blockIdx.x * blockDim.x + threadIdx.x;
    if (i == 0) {
        int ok = 1;
        #pragma unroll
        for (int q = 1; q < 64; q += 2) if (e[q] != 0u) ok = 0;
        g_is64 = ok;
    }
    if (i < NN) { g_cnt[i] = 0; g_need[i] = 0; }
}

// ---------------- need flags -------------------------------------------------
__global__ void need_kernel(const void* __restrict__ bi, const void* __restrict__ ni) {
    int m = blockIdx.x * blockDim.x + threadIdx.x;
    if (m >= MM) return;
    int is64 = g_is64;
    long long b = clampll(load_idx(bi, m, is64), 0, NB  - 1);
    long long n = clampll(load_idx(ni, m, is64), 0, ADJ - 1);
    g_need[(int)(b * ADJ + n)] = 1;
}

// ---------------- padded-CSR fill --------------------------------------------
__global__ __launch_bounds__(256) void fill_kernel(const void* __restrict__ ei) {
    int e = blockIdx.x * blockDim.x + threadIdx.x;
    if (e >= NE) return;
    int is64 = g_is64;
    int src = (int)clampll(load_idx(ei, e,                 is64), 0, NN - 1);
    int dst = (int)clampll(load_idx(ei, (long long)NE + e, is64), 0, NN - 1);
    int pos = atomicAdd(&g_cnt[dst], 1);
    if (pos < PAD) g_esrc[dst * PAD + pos] = src;
}

// ---------------- aggregation (R7 tree-add version; measured best) -----------
__global__ __launch_bounds__(256) void agg_kernel(
    const float* __restrict__ X, float* __restrict__ out, int use_mask)
{
    int w    = threadIdx.x >> 5;
    int lane = threadIdx.x & 31;
    int n    = blockIdx.x * 8 + w;
    if (n >= NN) return;
    if (use_mask && !g_need[n]) return;

    int s0 = n * PAD;
    int cn = min(g_cnt[n], PAD);
    const float4* __restrict__ Xv = (const float4*)X;

    float4 acc = make_float4(0.f, 0.f, 0.f, 0.f);
    int k = 0;
    for (; k + 8 <= cn; k += 8) {
        int idx[8];
        #pragma unroll
        for (int u = 0; u < 8; u++) idx[u] = __ldg(&g_esrc[s0 + k + u]);
        float4 v[8];
        #pragma unroll
        for (int u = 0; u < 8; u++) v[u] = __ldg(Xv + (long long)idx[u] * 32 + lane);
        float4 s0v, s1v, s2v, s3v, t0, t1, r;
        s0v.x=v[0].x+v[1].x; s0v.y=v[0].y+v[1].y; s0v.z=v[0].z+v[1].z; s0v.w=v[0].w+v[1].w;
        s1v.x=v[2].x+v[3].x; s1v.y=v[2].y+v[3].y; s1v.z=v[2].z+v[3].z; s1v.w=v[2].w+v[3].w;
        s2v.x=v[4].x+v[5].x; s2v.y=v[4].y+v[5].y; s2v.z=v[4].z+v[5].z; s2v.w=v[4].w+v[5].w;
        s3v.x=v[6].x+v[7].x; s3v.y=v[6].y+v[7].y; s3v.z=v[6].z+v[7].z; s3v.w=v[6].w+v[7].w;
        t0.x=s0v.x+s1v.x; t0.y=s0v.y+s1v.y; t0.z=s0v.z+s1v.z; t0.w=s0v.w+s1v.w;
        t1.x=s2v.x+s3v.x; t1.y=s2v.y+s3v.y; t1.z=s2v.z+s3v.z; t1.w=s2v.w+s3v.w;
        r.x=t0.x+t1.x; r.y=t0.y+t1.y; r.z=t0.z+t1.z; r.w=t0.w+t1.w;
        acc.x+=r.x; acc.y+=r.y; acc.z+=r.z; acc.w+=r.w;
    }
    for (; k < cn; k++) {
        int i0 = __ldg(&g_esrc[s0 + k]);
        float4 a = __ldg(Xv + (long long)i0 * 32 + lane);
        acc.x += a.x; acc.y += a.y; acc.z += a.z; acc.w += a.w;
    }
    ((float4*)out)[(long long)n * 32 + lane] = acc;
}

// ---------------- 128x128 weight folds ---------------------------------------
__global__ __launch_bounds__(128) void matmul128(
    const float* __restrict__ A, const float* __restrict__ B,
    const float* __restrict__ avec, const float* __restrict__ addv,
    float* __restrict__ C, float* __restrict__ cvec)
{
    __shared__ __align__(16) float sB[16 * DD];
    int j = threadIdx.x;
    int i = blockIdx.x;
    const float* arow = (i < DD) ? (A + i * DD) : avec;

    float acc = 0.f;
    for (int kc = 0; kc < DD; kc += 16) {
        __syncthreads();
        #pragma unroll
        for (int u = 0; u < 4; u++) {
            int off = u * 128 + j;
            ((float4*)sB)[off] = __ldg(((const float4*)(B + kc * DD)) + off);
        }
        __syncthreads();
        #pragma unroll
        for (int k = 0; k < 16; k++)
            acc = fmaf(__ldg(&arow[kc + k]), sB[k * DD + j], acc);
    }
    if (i < DD) C[i * DD + j] = acc;
    else        cvec[j] = acc + (addv ? __ldg(&addv[j]) : 0.f);
}

// ---------------- tf32 hi/lo split of a 128x128 matrix -----------------------
__global__ void split_tf32_kernel(const float* __restrict__ W,
                                  float* __restrict__ hi, float* __restrict__ lo)
{
    int i = blockIdx.x * blockDim.x + threadIdx.x;   // 16384 elems
    if (i >= DD * DD) return;
    float w  = __ldg(&W[i]);
    float hf = __uint_as_float(tf32_of(w));
    hi[i] = hf;
    lo[i] = __uint_as_float(tf32_of(w - hf));
}

// ---------------- gather + GEMM via tensor cores (3xTF32) --------------------
// Block: 256 thr = 8 warps; tile 64 rows x 128 cols. Warp w: rows (w&3)*16,
// cols (w>>2)*64 (8 n-tiles of m16n8k8). W hi/lo pre-split; X split on the fly.
#define SXP 132     // sX row stride (floats): banks (4m + k) % 32 -> conflict-free
#define SWP 136     // sW row stride (floats): banks (8k + n) % 32 -> conflict-free
__global__ __launch_bounds__(256) void gather_mm_tc(
    const float* __restrict__ X, const void* __restrict__ bi,
    const void* __restrict__ ni,
    const float* __restrict__ Whi, const float* __restrict__ Wlo,
    const float* __restrict__ bias,
    int use_deg, const float* __restrict__ c1,
    float* __restrict__ out)
{
    __shared__ __align__(16) float sX [64 * SXP];   // 33.8 KB
    __shared__ __align__(16) float sWh[8 * SWP];    // 4.3 KB
    __shared__ __align__(16) float sWl[8 * SWP];    // 4.3 KB
    __shared__ int sIdx[64];

    int t  = threadIdx.x;
    int m0 = blockIdx.x * 64;
    if (t < 64) {
        int is64 = g_is64;
        long long b = clampll(load_idx(bi, m0 + t, is64), 0, NB  - 1);
        long long n = clampll(load_idx(ni, m0 + t, is64), 0, ADJ - 1);
        sIdx[t] = (int)(b * ADJ + n);
    }
    __syncthreads();

    // gather full X rows once: warp per row-slice, float4 stores (aligned: SXP%4==0)
    #pragma unroll
    for (int i = 0; i < 8; i++) {
        int u = i * 256 + t;
        int r = u >> 5;
        int c = u & 31;
        float4 v = __ldg(((const float4*)(X + (long long)sIdx[r] * DD)) + c);
        *(float4*)(sX + r * SXP + c * 4) = v;
    }

    int w    = t >> 5;
    int lane = t & 31;
    int gid  = lane >> 2;      // 0..7
    int tig  = lane & 3;       // 0..3
    int wr   = (w & 3) * 16;   // row tile base
    int wc   = (w >> 2) * 64;  // col half base

    float c[8][4];
    #pragma unroll
    for (int nt = 0; nt < 8; nt++)
        #pragma unroll
        for (int q = 0; q < 4; q++) c[nt][q] = 0.f;

    for (int kc = 0; kc < DD; kc += 8) {
        __syncthreads();
        // stage W chunk rows kc..kc+7 (hi & lo): 256 float4 each, 1 per thread
        {
            int r4 = t >> 5;          // chunk row 0..7
            int cc = t & 31;          // float4 col
            *(float4*)(sWh + r4 * SWP + cc * 4) =
                __ldg(((const float4*)(Whi + (kc + r4) * DD)) + cc);
            *(float4*)(sWl + r4 * SWP + cc * 4) =
                __ldg(((const float4*)(Wlo + (kc + r4) * DD)) + cc);
        }
        __syncthreads();

        // A fragments (m16k8) from sX, split hi/lo on the fly
        float x0 = sX[(wr + gid    ) * SXP + kc + tig    ];
        float x1 = sX[(wr + gid + 8) * SXP + kc + tig    ];
        float x2 = sX[(wr + gid    ) * SXP + kc + tig + 4];
        float x3 = sX[(wr + gid + 8) * SXP + kc + tig + 4];
        unsigned ah0 = tf32_of(x0), ah1 = tf32_of(x1), ah2 = tf32_of(x2), ah3 = tf32_of(x3);
        unsigned al0 = tf32_of(x0 - __uint_as_float(ah0));
        unsigned al1 = tf32_of(x1 - __uint_as_float(ah1));
        unsigned al2 = tf32_of(x2 - __uint_as_float(ah2));
        unsigned al3 = tf32_of(x3 - __uint_as_float(ah3));

        #pragma unroll
        for (int nt = 0; nt < 8; nt++) {
            int nb = wc + nt * 8;
            unsigned bh0 = __float_as_uint(sWh[ tig      * SWP + nb + gid]);
            unsigned bh1 = __float_as_uint(sWh[(tig + 4) * SWP + nb + gid]);
            unsigned bl0 = __float_as_uint(sWl[ tig      * SWP + nb + gid]);
            unsigned bl1 = __float_as_uint(sWl[(tig + 4) * SWP + nb + gid]);
            mma_tf32(c[nt][0], c[nt][1], c[nt][2], c[nt][3],
                     ah0, ah1, ah2, ah3, bh0, bh1);                 // hi*hi
            mma_tf32(c[nt][0], c[nt][1], c[nt][2], c[nt][3],
                     ah0, ah1, ah2, ah3, bl0, bl1);                 // hi*lo
            mma_tf32(c[nt][0], c[nt][1], c[nt][2], c[nt][3],
                     al0, al1, al2, al3, bh0, bh1);                 // lo*hi
        }
    }

    // epilogue: D[row][col] += bias (+ deg*c1); c0,c1 -> row gid; c2,c3 -> row gid+8
    int r0l = wr + gid;
    int r1l = r0l + 8;
    float d0 = use_deg ? (float)g_cnt[sIdx[r0l]] : 0.f;
    float d1 = use_deg ? (float)g_cnt[sIdx[r1l]] : 0.f;
    float* orow0 = out + (long long)(m0 + r0l) * DD;
    float* orow1 = out + (long long)(m0 + r1l) * DD;
    #pragma unroll
    for (int nt = 0; nt < 8; nt++) {
        int j0 = wc + nt * 8 + 2 * tig;
        float bv0 = __ldg(&bias[j0]);
        float bv1 = __ldg(&bias[j0 + 1]);
        float cv0 = use_deg ? __ldg(&c1[j0])     : 0.f;
        float cv1 = use_deg ? __ldg(&c1[j0 + 1]) : 0.f;
        float2 o0, o1;
        o0.x = c[nt][0] + bv0 + d0 * cv0;
        o0.y = c[nt][1] + bv1 + d0 * cv1;
        o1.x = c[nt][2] + bv0 + d1 * cv0;
        o1.y = c[nt][3] + bv1 + d1 * cv1;
        *(float2*)(orow0 + j0) = o0;
        *(float2*)(orow1 + j0) = o1;
    }
}

// ---------------- launch -----------------------------------------------------
extern "C" void kernel_launch(void* const* d_in, const int* in_sizes, int n_in,
                              void* d_out, int out_size)
{
    const float* x0  = (const float*)d_in[0];
    const float* x1  = (const float*)d_in[1];
    const void*  ei  = d_in[2];
    const void*  b0  = d_in[3];
    const void*  n0  = d_in[4];
    const void*  b1i = d_in[5];
    const void*  n1i = d_in[6];
    const float* W1  = (const float*)d_in[7];
    const float* b1  = (const float*)d_in[8];
    const float* W2  = (const float*)d_in[9];
    const float* b2  = (const float*)d_in[10];
    const float* Wl  = (const float*)d_in[11];
    const float* bl  = (const float*)d_in[12];
    const float* Wfi = (const float*)d_in[13];
    const float* bfi = (const float*)d_in[14];
    float* out = (float*)d_out;

    float *agg1, *t2, *Wc, *Wall, *c0, *c1, *Wfh, *Wfl, *Wah, *Wal;
    cudaGetSymbolAddress((void**)&agg1, g_agg1);
    cudaGetSymbolAddress((void**)&t2,   g_t2);
    cudaGetSymbolAddress((void**)&Wc,   g_Wc);
    cudaGetSymbolAddress((void**)&Wall, g_Wall);
    cudaGetSymbolAddress((void**)&c0,   g_c0);
    cudaGetSymbolAddress((void**)&c1,   g_c1);
    cudaGetSymbolAddress((void**)&Wfh,  g_Wfi_h);
    cudaGetSymbolAddress((void**)&Wfl,  g_Wfi_l);
    cudaGetSymbolAddress((void**)&Wah,  g_Wall_h);
    cudaGetSymbolAddress((void**)&Wal,  g_Wall_l);

    static cudaStream_t s2 = nullptr;
    static cudaEvent_t  eA = nullptr, eB = nullptr;
    if (s2 == nullptr) {
        cudaStreamCreateWithFlags(&s2, cudaStreamNonBlocking);
        cudaEventCreateWithFlags(&eA, cudaEventDisableTiming);
        cudaEventCreateWithFlags(&eB, cudaEventDisableTiming);
    }

    // #0 main: detect + zero
    detect_zero_kernel<<<(NN + 255) / 256, 256>>>((const unsigned int*)ei);
    cudaEventRecord(eA, 0);

    // side stream: branch-0 + weight prep (gmm_tc at launch-call #3 for ncu)
    cudaStreamWaitEvent(s2, eA, 0);
    split_tf32_kernel<<<DD * DD / 256, 256, 0, s2>>>(Wfi, Wfh, Wfl);           // #1
    matmul128<<<DD + 1, DD, 0, s2>>>(W2, Wl, b2, bl, Wc, c0);                  // #2
    gather_mm_tc<<<MM / 64, 256, 0, s2>>>(x0, b0, n0, Wfh, Wfl, bfi,
                                          0, nullptr, out);                    // #3
    matmul128<<<DD + 1, DD, 0, s2>>>(W1, Wc, b1, nullptr, Wall, c1);           // #4
    split_tf32_kernel<<<DD * DD / 256, 256, 0, s2>>>(Wall, Wah, Wal);          // #5
    need_kernel<<<(MM + 255) / 256, 256, 0, s2>>>(b1i, n1i);                   // #6
    cudaEventRecord(eB, s2);

    // main stream: CSR fill + aggregation pass 1
    fill_kernel<<<NE / 256, 256>>>(ei);                                        // #7
    agg_kernel<<<(NN + 7) / 8, 256>>>(x1, agg1, 0);                            // #8

    // join
    cudaStreamWaitEvent(0, eB, 0);
    agg_kernel<<<(NN + 7) / 8, 256>>>(agg1, t2, 1);                            // #9
    gather_mm_tc<<<MM / 64, 256>>>(t2, b1i, n1i, Wah, Wal, c0,
                                   1, c1, out + (long long)MM * DD);           // #10
}

// round 11
// speedup vs baseline: 1.4574x; 1.0315x over previous
#include <cuda_runtime.h>
#include <cuda_bf16.h>

// Problem constants
#define NB     64
#define ADJ    1000
#define NN     (NB*ADJ)        // 64000 nodes
#define NE     (1<<20)         // edges
#define MM     32000           // selected pairs
#define DD     128             // feature dim
#define PAD    64              // padded CSR row slots

// ---------------- scratch ----------------------------------------------------
__device__ __align__(16) float g_agg1 [NN*DD];
__device__ __align__(16) float g_Wc    [DD*DD];
__device__ __align__(16) float g_Wall  [DD*DD];
__device__ __align__(16) float g_Wfi_h [DD*DD];
__device__ __align__(16) float g_Wfi_l [DD*DD];
__device__ __align__(16) float g_Wall_h[DD*DD];
__device__ __align__(16) float g_Wall_l[DD*DD];
__device__ __align__(16) float g_c0  [DD];
__device__ __align__(16) float g_c1  [DD];
__device__ __align__(16) int   g_esrc[NN*PAD];
__device__ __align__(16) int   g_cnt [NN];
__device__ int g_is64;

// ---------------- helpers ----------------------------------------------------
__device__ __forceinline__ long long load_idx(const void* p, long long i, int is64) {
    return is64 ? ((const long long*)p)[i] : (long long)((const int*)p)[i];
}
__device__ __forceinline__ long long clampll(long long v, long long lo, long long hi) {
    return v < lo ? lo : (v > hi ? hi : v);
}
__device__ __forceinline__ unsigned tf32_of(float x) {
    unsigned r; asm("cvt.rna.tf32.f32 %0, %1;" : "=r"(r) : "f"(x)); return r;
}
__device__ __forceinline__ void mma_tf32(
    float& c0, float& c1, float& c2, float& c3,
    unsigned a0, unsigned a1, unsigned a2, unsigned a3,
    unsigned b0, unsigned b1)
{
    asm volatile(
        "mma.sync.aligned.m16n8k8.row.col.f32.tf32.tf32.f32 "
        "{%0,%1,%2,%3}, {%4,%5,%6,%7}, {%8,%9}, {%0,%1,%2,%3};"
        : "+f"(c0), "+f"(c1), "+f"(c2), "+f"(c3)
        : "r"(a0), "r"(a1), "r"(a2), "r"(a3), "r"(b0), "r"(b1));
}

// ---------------- dtype detect + zero cnt ------------------------------------
__global__ void detect_zero_kernel(const unsigned int* __restrict__ e) {
    int i = blockIdx.x * blockDim.x + threadIdx.x;
    if (i == 0) {
        int ok = 1;
        #pragma unroll
        for (int q = 1; q < 64; q += 2) if (e[q] != 0u) ok = 0;
        g_is64 = ok;
    }
    if (i < NN) g_cnt[i] = 0;
}

// ---------------- padded-CSR fill, 4 edges/thread ----------------------------
__global__ __launch_bounds__(256) void fill_kernel(const void* __restrict__ ei) {
    int base = (blockIdx.x * 256 + threadIdx.x) * 4;
    int is64 = g_is64;
    #pragma unroll
    for (int u = 0; u < 4; u++) {
        int e = base + u;
        int src = (int)clampll(load_idx(ei, e,                 is64), 0, NN - 1);
        int dst = (int)clampll(load_idx(ei, (long long)NE + e, is64), 0, NN - 1);
        int pos = atomicAdd(&g_cnt[dst], 1);
        if (pos < PAD) g_esrc[dst * PAD + pos] = src;
    }
}

// ---------------- aggregation pass 1 (R7 tree-add; measured best) ------------
__global__ __launch_bounds__(256) void agg_kernel(
    const float* __restrict__ X, float* __restrict__ out)
{
    int w    = threadIdx.x >> 5;
    int lane = threadIdx.x & 31;
    int n    = blockIdx.x * 8 + w;
    if (n >= NN) return;

    int s0 = n * PAD;
    int cn = min(g_cnt[n], PAD);
    const float4* __restrict__ Xv = (const float4*)X;

    float4 acc = make_float4(0.f, 0.f, 0.f, 0.f);
    int k = 0;
    for (; k + 8 <= cn; k += 8) {
        int idx[8];
        #pragma unroll
        for (int u = 0; u < 8; u++) idx[u] = __ldg(&g_esrc[s0 + k + u]);
        float4 v[8];
        #pragma unroll
        for (int u = 0; u < 8; u++) v[u] = __ldg(Xv + (long long)idx[u] * 32 + lane);
        float4 s0v, s1v, s2v, s3v, t0, t1, r;
        s0v.x=v[0].x+v[1].x; s0v.y=v[0].y+v[1].y; s0v.z=v[0].z+v[1].z; s0v.w=v[0].w+v[1].w;
        s1v.x=v[2].x+v[3].x; s1v.y=v[2].y+v[3].y; s1v.z=v[2].z+v[3].z; s1v.w=v[2].w+v[3].w;
        s2v.x=v[4].x+v[5].x; s2v.y=v[4].y+v[5].y; s2v.z=v[4].z+v[5].z; s2v.w=v[4].w+v[5].w;
        s3v.x=v[6].x+v[7].x; s3v.y=v[6].y+v[7].y; s3v.z=v[6].z+v[7].z; s3v.w=v[6].w+v[7].w;
        t0.x=s0v.x+s1v.x; t0.y=s0v.y+s1v.y; t0.z=s0v.z+s1v.z; t0.w=s0v.w+s1v.w;
        t1.x=s2v.x+s3v.x; t1.y=s2v.y+s3v.y; t1.z=s2v.z+s3v.z; t1.w=s2v.w+s3v.w;
        r.x=t0.x+t1.x; r.y=t0.y+t1.y; r.z=t0.z+t1.z; r.w=t0.w+t1.w;
        acc.x+=r.x; acc.y+=r.y; acc.z+=r.z; acc.w+=r.w;
    }
    for (; k < cn; k++) {
        int i0 = __ldg(&g_esrc[s0 + k]);
        float4 a = __ldg(Xv + (long long)i0 * 32 + lane);
        acc.x += a.x; acc.y += a.y; acc.z += a.z; acc.w += a.w;
    }
    ((float4*)out)[(long long)n * 32 + lane] = acc;
}

// ---------------- 128x128 weight folds ---------------------------------------
__global__ __launch_bounds__(128) void matmul128(
    const float* __restrict__ A, const float* __restrict__ B,
    const float* __restrict__ avec, const float* __restrict__ addv,
    float* __restrict__ C, float* __restrict__ cvec)
{
    __shared__ __align__(16) float sB[16 * DD];
    int j = threadIdx.x;
    int i = blockIdx.x;
    const float* arow = (i < DD) ? (A + i * DD) : avec;

    float acc = 0.f;
    for (int kc = 0; kc < DD; kc += 16) {
        __syncthreads();
        #pragma unroll
        for (int u = 0; u < 4; u++) {
            int off = u * 128 + j;
            ((float4*)sB)[off] = __ldg(((const float4*)(B + kc * DD)) + off);
        }
        __syncthreads();
        #pragma unroll
        for (int k = 0; k < 16; k++)
            acc = fmaf(__ldg(&arow[kc + k]), sB[k * DD + j], acc);
    }
    if (i < DD) C[i * DD + j] = acc;
    else        cvec[j] = acc + (addv ? __ldg(&addv[j]) : 0.f);
}

// ---------------- tf32 hi/lo split -------------------------------------------
__global__ void split_tf32_kernel(const float* __restrict__ W,
                                  float* __restrict__ hi, float* __restrict__ lo)
{
    int i = blockIdx.x * blockDim.x + threadIdx.x;
    if (i >= DD * DD) return;
    float w  = __ldg(&W[i]);
    float hf = __uint_as_float(tf32_of(w));
    hi[i] = hf;
    lo[i] = __uint_as_float(tf32_of(w - hf));
}

// ---------------- shared MMA core (3xTF32, 64x128 tile from sX) --------------
#define SXP 132
#define SWP 136

// MMA loop + epilogue, reading X tile from sX, W from gmem hi/lo. dscale per row.
__device__ __forceinline__ void mma_tile_and_store(
    float* sX, float* sWh, float* sWl, const int* sIdx,
    const float* __restrict__ Whi, const float* __restrict__ Wlo,
    const float* __restrict__ bias, int use_deg, const float* __restrict__ c1,
    float* __restrict__ out, int m0, int t)
{
    int w    = t >> 5;
    int lane = t & 31;
    int gid  = lane >> 2;
    int tig  = lane & 3;
    int wr   = (w & 3) * 16;
    int wc   = (w >> 2) * 64;

    float c[8][4];
    #pragma unroll
    for (int nt = 0; nt < 8; nt++)
        #pragma unroll
        for (int q = 0; q < 4; q++) c[nt][q] = 0.f;

    for (int kc = 0; kc < DD; kc += 8) {
        __syncthreads();
        {
            int r4 = t >> 5;
            int cc = t & 31;
            *(float4*)(sWh + r4 * SWP + cc * 4) =
                __ldg(((const float4*)(Whi + (kc + r4) * DD)) + cc);
            *(float4*)(sWl + r4 * SWP + cc * 4) =
                __ldg(((const float4*)(Wlo + (kc + r4) * DD)) + cc);
        }
        __syncthreads();

        float x0 = sX[(wr + gid    ) * SXP + kc + tig    ];
        float x1 = sX[(wr + gid + 8) * SXP + kc + tig    ];
        float x2 = sX[(wr + gid    ) * SXP + kc + tig + 4];
        float x3 = sX[(wr + gid + 8) * SXP + kc + tig + 4];
        unsigned ah0 = tf32_of(x0), ah1 = tf32_of(x1), ah2 = tf32_of(x2), ah3 = tf32_of(x3);
        unsigned al0 = tf32_of(x0 - __uint_as_float(ah0));
        unsigned al1 = tf32_of(x1 - __uint_as_float(ah1));
        unsigned al2 = tf32_of(x2 - __uint_as_float(ah2));
        unsigned al3 = tf32_of(x3 - __uint_as_float(ah3));

        #pragma unroll
        for (int nt = 0; nt < 8; nt++) {
            int nb = wc + nt * 8;
            unsigned bh0 = __float_as_uint(sWh[ tig      * SWP + nb + gid]);
            unsigned bh1 = __float_as_uint(sWh[(tig + 4) * SWP + nb + gid]);
            unsigned bl0 = __float_as_uint(sWl[ tig      * SWP + nb + gid]);
            unsigned bl1 = __float_as_uint(sWl[(tig + 4) * SWP + nb + gid]);
            mma_tf32(c[nt][0], c[nt][1], c[nt][2], c[nt][3],
                     ah0, ah1, ah2, ah3, bh0, bh1);
            mma_tf32(c[nt][0], c[nt][1], c[nt][2], c[nt][3],
                     ah0, ah1, ah2, ah3, bl0, bl1);
            mma_tf32(c[nt][0], c[nt][1], c[nt][2], c[nt][3],
                     al0, al1, al2, al3, bh0, bh1);
        }
    }

    int r0l = wr + gid;
    int r1l = r0l + 8;
    float d0 = use_deg ? (float)g_cnt[sIdx[r0l]] : 0.f;
    float d1 = use_deg ? (float)g_cnt[sIdx[r1l]] : 0.f;
    float* orow0 = out + (long long)(m0 + r0l) * DD;
    float* orow1 = out + (long long)(m0 + r1l) * DD;
    #pragma unroll
    for (int nt = 0; nt < 8; nt++) {
        int j0 = wc + nt * 8 + 2 * tig;
        float bv0 = __ldg(&bias[j0]);
        float bv1 = __ldg(&bias[j0 + 1]);
        float cv0 = use_deg ? __ldg(&c1[j0])     : 0.f;
        float cv1 = use_deg ? __ldg(&c1[j0 + 1]) : 0.f;
        float2 o0, o1;
        o0.x = c[nt][0] + bv0 + d0 * cv0;
        o0.y = c[nt][1] + bv1 + d0 * cv1;
        o1.x = c[nt][2] + bv0 + d1 * cv0;
        o1.y = c[nt][3] + bv1 + d1 * cv1;
        *(float2*)(orow0 + j0) = o0;
        *(float2*)(orow1 + j0) = o1;
    }
}

// ---------------- branch 0: gather rows -> GEMM (tc) -------------------------
__global__ __launch_bounds__(256) void gather_mm_tc(
    const float* __restrict__ X, const void* __restrict__ bi,
    const void* __restrict__ ni,
    const float* __restrict__ Whi, const float* __restrict__ Wlo,
    const float* __restrict__ bias, float* __restrict__ out)
{
    __shared__ __align__(16) float sX [64 * SXP];
    __shared__ __align__(16) float sWh[8 * SWP];
    __shared__ __align__(16) float sWl[8 * SWP];
    __shared__ int sIdx[64];

    int t  = threadIdx.x;
    int m0 = blockIdx.x * 64;
    if (t < 64) {
        int is64 = g_is64;
        long long b = clampll(load_idx(bi, m0 + t, is64), 0, NB  - 1);
        long long n = clampll(load_idx(ni, m0 + t, is64), 0, ADJ - 1);
        sIdx[t] = (int)(b * ADJ + n);
    }
    __syncthreads();

    #pragma unroll
    for (int i = 0; i < 8; i++) {
        int u = i * 256 + t;
        int r = u >> 5;
        int c = u & 31;
        float4 v = __ldg(((const float4*)(X + (long long)sIdx[r] * DD)) + c);
        *(float4*)(sX + r * SXP + c * 4) = v;
    }

    mma_tile_and_store(sX, sWh, sWl, sIdx, Whi, Wlo, bias, 0, nullptr, out, m0, t);
}

// ---------------- branch 1 FUSED: aggregate (A@agg1) row in smem -> GEMM -----
__global__ __launch_bounds__(256) void agg_mm_tc(
    const float* __restrict__ Xagg, const void* __restrict__ bi,
    const void* __restrict__ ni,
    const float* __restrict__ Whi, const float* __restrict__ Wlo,
    const float* __restrict__ bias, const float* __restrict__ c1,
    float* __restrict__ out)
{
    __shared__ __align__(16) float sX [64 * SXP];
    __shared__ __align__(16) float sWh[8 * SWP];
    __shared__ __align__(16) float sWl[8 * SWP];
    __shared__ int sIdx[64];

    int t  = threadIdx.x;
    int m0 = blockIdx.x * 64;
    if (t < 64) {
        int is64 = g_is64;
        long long b = clampll(load_idx(bi, m0 + t, is64), 0, NB  - 1);
        long long n = clampll(load_idx(ni, m0 + t, is64), 0, ADJ - 1);
        sIdx[t] = (int)(b * ADJ + n);
    }
    __syncthreads();

    // aggregate phase: warp w computes rows w*8..w*8+7; lane owns float4 chunk.
    {
        int w    = t >> 5;
        int lane = t & 31;
        const float4* __restrict__ Xv = (const float4*)Xagg;
        #pragma unroll 1
        for (int q = 0; q < 8; q++) {
            int row = w * 8 + q;
            int n   = sIdx[row];
            int s0  = n * PAD;
            int cn  = min(g_cnt[n], PAD);
            float4 acc = make_float4(0.f, 0.f, 0.f, 0.f);
            int k = 0;
            for (; k + 8 <= cn; k += 8) {
                int idx[8];
                #pragma unroll
                for (int u = 0; u < 8; u++) idx[u] = __ldg(&g_esrc[s0 + k + u]);
                float4 v[8];
                #pragma unroll
                for (int u = 0; u < 8; u++) v[u] = __ldg(Xv + (long long)idx[u] * 32 + lane);
                float4 s0v, s1v, s2v, s3v, t0, t1, r;
                s0v.x=v[0].x+v[1].x; s0v.y=v[0].y+v[1].y; s0v.z=v[0].z+v[1].z; s0v.w=v[0].w+v[1].w;
                s1v.x=v[2].x+v[3].x; s1v.y=v[2].y+v[3].y; s1v.z=v[2].z+v[3].z; s1v.w=v[2].w+v[3].w;
                s2v.x=v[4].x+v[5].x; s2v.y=v[4].y+v[5].y; s2v.z=v[4].z+v[5].z; s2v.w=v[4].w+v[5].w;
                s3v.x=v[6].x+v[7].x; s3v.y=v[6].y+v[7].y; s3v.z=v[6].z+v[7].z; s3v.w=v[6].w+v[7].w;
                t0.x=s0v.x+s1v.x; t0.y=s0v.y+s1v.y; t0.z=s0v.z+s1v.z; t0.w=s0v.w+s1v.w;
                t1.x=s2v.x+s3v.x; t1.y=s2v.y+s3v.y; t1.z=s2v.z+s3v.z; t1.w=s2v.w+s3v.w;
                r.x=t0.x+t1.x; r.y=t0.y+t1.y; r.z=t0.z+t1.z; r.w=t0.w+t1.w;
                acc.x+=r.x; acc.y+=r.y; acc.z+=r.z; acc.w+=r.w;
            }
            for (; k < cn; k++) {
                int i0 = __ldg(&g_esrc[s0 + k]);
                float4 a = __ldg(Xv + (long long)i0 * 32 + lane);
                acc.x += a.x; acc.y += a.y; acc.z += a.z; acc.w += a.w;
            }
            *(float4*)(sX + row * SXP + lane * 4) = acc;
        }
    }

    mma_tile_and_store(sX, sWh, sWl, sIdx, Whi, Wlo, bias, 1, c1, out, m0, t);
}

// ---------------- launch -----------------------------------------------------
extern "C" void kernel_launch(void* const* d_in, const int* in_sizes, int n_in,
                              void* d_out, int out_size)
{
    const float* x0  = (const float*)d_in[0];
    const float* x1  = (const float*)d_in[1];
    const void*  ei  = d_in[2];
    const void*  b0  = d_in[3];
    const void*  n0  = d_in[4];
    const void*  b1i = d_in[5];
    const void*  n1i = d_in[6];
    const float* W1  = (const float*)d_in[7];
    const float* b1  = (const float*)d_in[8];
    const float* W2  = (const float*)d_in[9];
    const float* b2  = (const float*)d_in[10];
    const float* Wl  = (const float*)d_in[11];
    const float* bl  = (const float*)d_in[12];
    const float* Wfi = (const float*)d_in[13];
    const float* bfi = (const float*)d_in[14];
    float* out = (float*)d_out;

    float *agg1, *Wc, *Wall, *c0, *c1, *Wfh, *Wfl, *Wah, *Wal;
    cudaGetSymbolAddress((void**)&agg1, g_agg1);
    cudaGetSymbolAddress((void**)&Wc,   g_Wc);
    cudaGetSymbolAddress((void**)&Wall, g_Wall);
    cudaGetSymbolAddress((void**)&c0,   g_c0);
    cudaGetSymbolAddress((void**)&c1,   g_c1);
    cudaGetSymbolAddress((void**)&Wfh,  g_Wfi_h);
    cudaGetSymbolAddress((void**)&Wfl,  g_Wfi_l);
    cudaGetSymbolAddress((void**)&Wah,  g_Wall_h);
    cudaGetSymbolAddress((void**)&Wal,  g_Wall_l);

    static cudaStream_t s2 = nullptr;
    static cudaEvent_t  eA = nullptr, eB = nullptr;
    if (s2 == nullptr) {
        cudaStreamCreateWithFlags(&s2, cudaStreamNonBlocking);
        cudaEventCreateWithFlags(&eA, cudaEventDisableTiming);
        cudaEventCreateWithFlags(&eB, cudaEventDisableTiming);
    }

    // #0 main: detect + zero cnt
    detect_zero_kernel<<<(NN + 255) / 256, 256>>>((const unsigned int*)ei);
    cudaEventRecord(eA, 0);

    // side stream: branch 0 + weight prep
    cudaStreamWaitEvent(s2, eA, 0);
    split_tf32_kernel<<<DD * DD / 256, 256, 0, s2>>>(Wfi, Wfh, Wfl);           // #1
    matmul128<<<DD + 1, DD, 0, s2>>>(W2, Wl, b2, bl, Wc, c0);                  // #2
    gather_mm_tc<<<MM / 64, 256, 0, s2>>>(x0, b0, n0, Wfh, Wfl, bfi, out);     // #3
    matmul128<<<DD + 1, DD, 0, s2>>>(W1, Wc, b1, nullptr, Wall, c1);           // #4
    split_tf32_kernel<<<DD * DD / 256, 256, 0, s2>>>(Wall, Wah, Wal);          // #5
    cudaEventRecord(eB, s2);

    // main stream: CSR fill + aggregation pass 1
    fill_kernel<<<NE / 1024, 256>>>(ei);                                       // #6
    agg_kernel<<<(NN + 7) / 8, 256>>>(x1, agg1);                               // #7

    // join: fused branch-1 (aggregate + GEMM), replaces agg2 + gather_mm
    cudaStreamWaitEvent(0, eB, 0);
    agg_mm_tc<<<MM / 64, 256>>>(agg1, b1i, n1i, Wah, Wal, c0, c1,
                                out + (long long)MM * DD);                     // #8
}

// round 13
// speedup vs baseline: 1.7194x; 1.1798x over previous
#include <cuda_runtime.h>
#include <cuda_fp16.h>

// Problem constants
#define NB     64
#define ADJ    1000
#define NN     (NB*ADJ)        // 64000 nodes
#define NE     (1<<20)         // edges
#define MM     32000           // selected pairs
#define DD     128             // feature dim
#define PAD    64              // padded CSR row slots

// ---------------- scratch ----------------------------------------------------
__device__ __align__(16) __half g_x1h  [NN*DD];  // x1 in fp16 (16 MB)
__device__ __align__(16) __half g_agg1h[NN*DD];  // A@x1 in fp16 (16 MB)
__device__ __align__(16) float g_Wc    [DD*DD];
__device__ __align__(16) float g_Wall  [DD*DD];
__device__ __align__(16) float g_Wfi_h [DD*DD];
__device__ __align__(16) float g_Wfi_l [DD*DD];
__device__ __align__(16) float g_Wall_h[DD*DD];
__device__ __align__(16) float g_Wall_l[DD*DD];
__device__ __align__(16) float g_c0  [DD];
__device__ __align__(16) float g_c1  [DD];
__device__ __align__(16) int   g_esrc[NN*PAD];
__device__ __align__(16) int   g_cnt [NN];
__device__ int g_is64;

// ---------------- helpers ----------------------------------------------------
__device__ __forceinline__ long long load_idx(const void* p, long long i, int is64) {
    return is64 ? ((const long long*)p)[i] : (long long)((const int*)p)[i];
}
__device__ __forceinline__ long long clampll(long long v, long long lo, long long hi) {
    return v < lo ? lo : (v > hi ? hi : v);
}
__device__ __forceinline__ unsigned tf32_of(float x) {
    unsigned r; asm("cvt.rna.tf32.f32 %0, %1;" : "=r"(r) : "f"(x)); return r;
}
__device__ __forceinline__ void mma_tf32(
    float& c0, float& c1, float& c2, float& c3,
    unsigned a0, unsigned a1, unsigned a2, unsigned a3,
    unsigned b0, unsigned b1)
{
    asm volatile(
        "mma.sync.aligned.m16n8k8.row.col.f32.tf32.tf32.f32 "
        "{%0,%1,%2,%3}, {%4,%5,%6,%7}, {%8,%9}, {%0,%1,%2,%3};"
        : "+f"(c0), "+f"(c1), "+f"(c2), "+f"(c3)
        : "r"(a0), "r"(a1), "r"(a2), "r"(a3), "r"(b0), "r"(b1));
}
// unpack uint2 (4 fp16) and add into float4 accumulator
__device__ __forceinline__ void acc_f16x4(float4& acc, uint2 v) {
    __half2 p0 = *(__half2*)&v.x;
    __half2 p1 = *(__half2*)&v.y;
    float2 f0 = __half22float2(p0);
    float2 f1 = __half22float2(p1);
    acc.x += f0.x; acc.y += f0.y; acc.z += f1.x; acc.w += f1.y;
}

// ---------------- dtype detect + zero cnt ------------------------------------
__global__ void detect_zero_kernel(const unsigned int* __restrict__ e) {
    int i = blockIdx.x * blockDim.x + threadIdx.x;
    if (i == 0) {
        int ok = 1;
        #pragma unroll
        for (int q = 1; q < 64; q += 2) if (e[q] != 0u) ok = 0;
        g_is64 = ok;
    }
    if (i < NN) g_cnt[i] = 0;
}

// ---------------- fp32 -> fp16 conversion ------------------------------------
__global__ __launch_bounds__(256) void conv_f16_kernel(
    const float* __restrict__ X, __half* __restrict__ Y)
{
    int i = blockIdx.x * blockDim.x + threadIdx.x;   // one per 4 elems
    if (i >= NN * DD / 4) return;
    float4 v = __ldg(((const float4*)X) + i);
    __half2 a = __float22half2_rn(make_float2(v.x, v.y));
    __half2 b = __float22half2_rn(make_float2(v.z, v.w));
    uint2 o; o.x = *(unsigned*)&a; o.y = *(unsigned*)&b;
    ((uint2*)Y)[i] = o;
}

// ---------------- padded-CSR fill, 4 edges/thread ----------------------------
__global__ __launch_bounds__(256) void fill_kernel(const void* __restrict__ ei) {
    int base = (blockIdx.x * 256 + threadIdx.x) * 4;
    int is64 = g_is64;
    #pragma unroll
    for (int u = 0; u < 4; u++) {
        int e = base + u;
        int src = (int)clampll(load_idx(ei, e,                 is64), 0, NN - 1);
        int dst = (int)clampll(load_idx(ei, (long long)NE + e, is64), 0, NN - 1);
        int pos = atomicAdd(&g_cnt[dst], 1);
        if (pos < PAD) g_esrc[dst * PAD + pos] = src;
    }
}

// ---------------- agg pass 1: fp16 rows -> fp32 acc -> fp16 out --------------
// warp per node; lane owns 4 columns (uint2 = 4 fp16, 8B); row = 32 uint2.
__global__ __launch_bounds__(256) void agg1h_kernel(
    const __half* __restrict__ Xh, __half* __restrict__ Oh)
{
    int w    = threadIdx.x >> 5;
    int lane = threadIdx.x & 31;
    int n    = blockIdx.x * 8 + w;
    if (n >= NN) return;

    int s0 = n * PAD;
    int cn = min(g_cnt[n], PAD);
    const uint2* __restrict__ Xv = (const uint2*)Xh;

    float4 acc = make_float4(0.f, 0.f, 0.f, 0.f);
    int k = 0;
    for (; k + 8 <= cn; k += 8) {
        int idx[8];
        #pragma unroll
        for (int u = 0; u < 8; u++) idx[u] = __ldg(&g_esrc[s0 + k + u]);
        uint2 v[8];
        #pragma unroll
        for (int u = 0; u < 8; u++) v[u] = __ldg(Xv + (long long)idx[u] * 32 + lane);
        #pragma unroll
        for (int u = 0; u < 8; u++) acc_f16x4(acc, v[u]);
    }
    for (; k < cn; k++) {
        int i0 = __ldg(&g_esrc[s0 + k]);
        acc_f16x4(acc, __ldg(Xv + (long long)i0 * 32 + lane));
    }
    __half2 a = __float22half2_rn(make_float2(acc.x, acc.y));
    __half2 b = __float22half2_rn(make_float2(acc.z, acc.w));
    uint2 o; o.x = *(unsigned*)&a; o.y = *(unsigned*)&b;
    ((uint2*)Oh)[(long long)n * 32 + lane] = o;
}

// ---------------- 128x128 weight folds ---------------------------------------
__global__ __launch_bounds__(128) void matmul128(
    const float* __restrict__ A, const float* __restrict__ B,
    const float* __restrict__ avec, const float* __restrict__ addv,
    float* __restrict__ C, float* __restrict__ cvec)
{
    __shared__ __align__(16) float sB[16 * DD];
    int j = threadIdx.x;
    int i = blockIdx.x;
    const float* arow = (i < DD) ? (A + i * DD) : avec;

    float acc = 0.f;
    for (int kc = 0; kc < DD; kc += 16) {
        __syncthreads();
        #pragma unroll
        for (int u = 0; u < 4; u++) {
            int off = u * 128 + j;
            ((float4*)sB)[off] = __ldg(((const float4*)(B + kc * DD)) + off);
        }
        __syncthreads();
        #pragma unroll
        for (int k = 0; k < 16; k++)
            acc = fmaf(__ldg(&arow[kc + k]), sB[k * DD + j], acc);
    }
    if (i < DD) C[i * DD + j] = acc;
    else        cvec[j] = acc + (addv ? __ldg(&addv[j]) : 0.f);
}

// ---------------- tf32 hi/lo split -------------------------------------------
__global__ void split_tf32_kernel(const float* __restrict__ W,
                                  float* __restrict__ hi, float* __restrict__ lo)
{
    int i = blockIdx.x * blockDim.x + threadIdx.x;
    if (i >= DD * DD) return;
    float w  = __ldg(&W[i]);
    float hf = __uint_as_float(tf32_of(w));
    hi[i] = hf;
    lo[i] = __uint_as_float(tf32_of(w - hf));
}

// ---------------- shared MMA core (3xTF32, 64x128 tile from sX) --------------
#define SXP 132
#define SWP 136

__device__ __forceinline__ void mma_tile_and_store(
    float* sX, float* sWh, float* sWl, const int* sIdx,
    const float* __restrict__ Whi, const float* __restrict__ Wlo,
    const float* __restrict__ bias, int use_deg, const float* __restrict__ c1,
    float* __restrict__ out, int m0, int t)
{
    int w    = t >> 5;
    int lane = t & 31;
    int gid  = lane >> 2;
    int tig  = lane & 3;
    int wr   = (w & 3) * 16;
    int wc   = (w >> 2) * 64;

    float c[8][4];
    #pragma unroll
    for (int nt = 0; nt < 8; nt++)
        #pragma unroll
        for (int q = 0; q < 4; q++) c[nt][q] = 0.f;

    for (int kc = 0; kc < DD; kc += 8) {
        __syncthreads();
        {
            int r4 = t >> 5;
            int cc = t & 31;
            *(float4*)(sWh + r4 * SWP + cc * 4) =
                __ldg(((const float4*)(Whi + (kc + r4) * DD)) + cc);
            *(float4*)(sWl + r4 * SWP + cc * 4) =
                __ldg(((const float4*)(Wlo + (kc + r4) * DD)) + cc);
        }
        __syncthreads();

        float x0 = sX[(wr + gid    ) * SXP + kc + tig    ];
        float x1 = sX[(wr + gid + 8) * SXP + kc + tig    ];
        float x2 = sX[(wr + gid    ) * SXP + kc + tig + 4];
        float x3 = sX[(wr + gid + 8) * SXP + kc + tig + 4];
        unsigned ah0 = tf32_of(x0), ah1 = tf32_of(x1), ah2 = tf32_of(x2), ah3 = tf32_of(x3);
        unsigned al0 = tf32_of(x0 - __uint_as_float(ah0));
        unsigned al1 = tf32_of(x1 - __uint_as_float(ah1));
        unsigned al2 = tf32_of(x2 - __uint_as_float(ah2));
        unsigned al3 = tf32_of(x3 - __uint_as_float(ah3));

        #pragma unroll
        for (int nt = 0; nt < 8; nt++) {
            int nb = wc + nt * 8;
            unsigned bh0 = __float_as_uint(sWh[ tig      * SWP + nb + gid]);
            unsigned bh1 = __float_as_uint(sWh[(tig + 4) * SWP + nb + gid]);
            unsigned bl0 = __float_as_uint(sWl[ tig      * SWP + nb + gid]);
            unsigned bl1 = __float_as_uint(sWl[(tig + 4) * SWP + nb + gid]);
            mma_tf32(c[nt][0], c[nt][1], c[nt][2], c[nt][3],
                     ah0, ah1, ah2, ah3, bh0, bh1);
            mma_tf32(c[nt][0], c[nt][1], c[nt][2], c[nt][3],
                     ah0, ah1, ah2, ah3, bl0, bl1);
            mma_tf32(c[nt][0], c[nt][1], c[nt][2], c[nt][3],
                     al0, al1, al2, al3, bh0, bh1);
        }
    }

    int r0l = wr + gid;
    int r1l = r0l + 8;
    float d0 = use_deg ? (float)g_cnt[sIdx[r0l]] : 0.f;
    float d1 = use_deg ? (float)g_cnt[sIdx[r1l]] : 0.f;
    float* orow0 = out + (long long)(m0 + r0l) * DD;
    float* orow1 = out + (long long)(m0 + r1l) * DD;
    #pragma unroll
    for (int nt = 0; nt < 8; nt++) {
        int j0 = wc + nt * 8 + 2 * tig;
        float bv0 = __ldg(&bias[j0]);
        float bv1 = __ldg(&bias[j0 + 1]);
        float cv0 = use_deg ? __ldg(&c1[j0])     : 0.f;
        float cv1 = use_deg ? __ldg(&c1[j0 + 1]) : 0.f;
        float2 o0, o1;
        o0.x = c[nt][0] + bv0 + d0 * cv0;
        o0.y = c[nt][1] + bv1 + d0 * cv1;
        o1.x = c[nt][2] + bv0 + d1 * cv0;
        o1.y = c[nt][3] + bv1 + d1 * cv1;
        *(float2*)(orow0 + j0) = o0;
        *(float2*)(orow1 + j0) = o1;
    }
}

// ---------------- branch 0: gather fp32 rows -> GEMM (tc) --------------------
__global__ __launch_bounds__(256) void gather_mm_tc(
    const float* __restrict__ X, const void* __restrict__ bi,
    const void* __restrict__ ni,
    const float* __restrict__ Whi, const float* __restrict__ Wlo,
    const float* __restrict__ bias, float* __restrict__ out)
{
    __shared__ __align__(16) float sX [64 * SXP];
    __shared__ __align__(16) float sWh[8 * SWP];
    __shared__ __align__(16) float sWl[8 * SWP];
    __shared__ int sIdx[64];

    int t  = threadIdx.x;
    int m0 = blockIdx.x * 64;
    if (t < 64) {
        int is64 = g_is64;
        long long b = clampll(load_idx(bi, m0 + t, is64), 0, NB  - 1);
        long long n = clampll(load_idx(ni, m0 + t, is64), 0, ADJ - 1);
        sIdx[t] = (int)(b * ADJ + n);
    }
    __syncthreads();

    #pragma unroll
    for (int i = 0; i < 8; i++) {
        int u = i * 256 + t;
        int r = u >> 5;
        int c = u & 31;
        float4 v = __ldg(((const float4*)(X + (long long)sIdx[r] * DD)) + c);
        *(float4*)(sX + r * SXP + c * 4) = v;
    }

    mma_tile_and_store(sX, sWh, sWl, sIdx, Whi, Wlo, bias, 0, nullptr, out, m0, t);
}

// ---------------- branch 1 FUSED: aggregate fp16 rows in smem -> GEMM --------
// fp32 accumulators feed the GEMM directly (no extra rounding on this hop).
__global__ __launch_bounds__(256) void agg_mm_tc(
    const __half* __restrict__ Xh, const void* __restrict__ bi,
    const void* __restrict__ ni,
    const float* __restrict__ Whi, const float* __restrict__ Wlo,
    const float* __restrict__ bias, const float* __restrict__ c1,
    float* __restrict__ out)
{
    __shared__ __align__(16) float sX [64 * SXP];
    __shared__ __align__(16) float sWh[8 * SWP];
    __shared__ __align__(16) float sWl[8 * SWP];
    __shared__ int sIdx[64];

    int t  = threadIdx.x;
    int m0 = blockIdx.x * 64;
    if (t < 64) {
        int is64 = g_is64;
        long long b = clampll(load_idx(bi, m0 + t, is64), 0, NB  - 1);
        long long n = clampll(load_idx(ni, m0 + t, is64), 0, ADJ - 1);
        sIdx[t] = (int)(b * ADJ + n);
    }
    __syncthreads();

    // aggregate phase: warp w computes rows w*8..w*8+7; lane owns 4 cols (uint2)
    {
        int w    = t >> 5;
        int lane = t & 31;
        const uint2* __restrict__ Xv = (const uint2*)Xh;
        #pragma unroll 1
        for (int q = 0; q < 8; q++) {
            int row = w * 8 + q;
            int n   = sIdx[row];
            int s0  = n * PAD;
            int cn  = min(g_cnt[n], PAD);
            float4 acc = make_float4(0.f, 0.f, 0.f, 0.f);
            int k = 0;
            for (; k + 8 <= cn; k += 8) {
                int idx[8];
                #pragma unroll
                for (int u = 0; u < 8; u++) idx[u] = __ldg(&g_esrc[s0 + k + u]);
                uint2 v[8];
                #pragma unroll
                for (int u = 0; u < 8; u++) v[u] = __ldg(Xv + (long long)idx[u] * 32 + lane);
                #pragma unroll
                for (int u = 0; u < 8; u++) acc_f16x4(acc, v[u]);
            }
            for (; k < cn; k++) {
                int i0 = __ldg(&g_esrc[s0 + k]);
                acc_f16x4(acc, __ldg(Xv + (long long)i0 * 32 + lane));
            }
            *(float4*)(sX + row * SXP + lane * 4) = acc;
        }
    }

    mma_tile_and_store(sX, sWh, sWl, sIdx, Whi, Wlo, bias, 1, c1, out, m0, t);
}

// ---------------- launch -----------------------------------------------------
extern "C" void kernel_launch(void* const* d_in, const int* in_sizes, int n_in,
                              void* d_out, int out_size)
{
    const float* x0  = (const float*)d_in[0];
    const float* x1  = (const float*)d_in[1];
    const void*  ei  = d_in[2];
    const void*  b0  = d_in[3];
    const void*  n0  = d_in[4];
    const void*  b1i = d_in[5];
    const void*  n1i = d_in[6];
    const float* W1  = (const float*)d_in[7];
    const float* b1  = (const float*)d_in[8];
    const float* W2  = (const float*)d_in[9];
    const float* b2  = (const float*)d_in[10];
    const float* Wl  = (const float*)d_in[11];
    const float* bl  = (const float*)d_in[12];
    const float* Wfi = (const float*)d_in[13];
    const float* bfi = (const float*)d_in[14];
    float* out = (float*)d_out;

    float *Wc, *Wall, *c0, *c1, *Wfh, *Wfl, *Wah, *Wal;
    __half *x1h, *agg1h;
    cudaGetSymbolAddress((void**)&x1h,   g_x1h);
    cudaGetSymbolAddress((void**)&agg1h, g_agg1h);
    cudaGetSymbolAddress((void**)&Wc,    g_Wc);
    cudaGetSymbolAddress((void**)&Wall,  g_Wall);
    cudaGetSymbolAddress((void**)&c0,    g_c0);
    cudaGetSymbolAddress((void**)&c1,    g_c1);
    cudaGetSymbolAddress((void**)&Wfh,   g_Wfi_h);
    cudaGetSymbolAddress((void**)&Wfl,   g_Wfi_l);
    cudaGetSymbolAddress((void**)&Wah,   g_Wall_h);
    cudaGetSymbolAddress((void**)&Wal,   g_Wall_l);

    static cudaStream_t s2 = nullptr, s3 = nullptr;
    static cudaEvent_t  eA = nullptr, eB = nullptr, eC = nullptr, eD = nullptr;
    if (s2 == nullptr) {
        cudaStreamCreateWithFlags(&s2, cudaStreamNonBlocking);
        cudaStreamCreateWithFlags(&s3, cudaStreamNonBlocking);
        cudaEventCreateWithFlags(&eA, cudaEventDisableTiming);
        cudaEventCreateWithFlags(&eB, cudaEventDisableTiming);
        cudaEventCreateWithFlags(&eC, cudaEventDisableTiming);
        cudaEventCreateWithFlags(&eD, cudaEventDisableTiming);
    }

    // #0 main: detect + zero cnt
    detect_zero_kernel<<<(NN + 255) / 256, 256>>>((const unsigned int*)ei);
    cudaEventRecord(eA, 0);

    // #1 s2: x1 -> fp16 (needed by agg1h on main)
    cudaStreamWaitEvent(s2, eA, 0);
    conv_f16_kernel<<<NN * DD / 4 / 256, 256, 0, s2>>>(x1, x1h);
    cudaEventRecord(eC, s2);

    // #2 main: padded-CSR fill
    fill_kernel<<<NE / 1024, 256>>>(ei);

    // #3 main: aggregation pass 1 (fp16) -- ncu profile slot
    cudaStreamWaitEvent(0, eC, 0);
    agg1h_kernel<<<(NN + 7) / 8, 256>>>(x1h, agg1h);

    // s2 continues: branch 0 (fp32 path)
    split_tf32_kernel<<<DD * DD / 256, 256, 0, s2>>>(Wfi, Wfh, Wfl);           // #4
    gather_mm_tc<<<MM / 64, 256, 0, s2>>>(x0, b0, n0, Wfh, Wfl, bfi, out);     // #5
    cudaEventRecord(eB, s2);

    // s3: weight folds for branch 1
    cudaStreamWaitEvent(s3, eA, 0);
    matmul128<<<DD + 1, DD, 0, s3>>>(W2, Wl, b2, bl, Wc, c0);                  // #6
    matmul128<<<DD + 1, DD, 0, s3>>>(W1, Wc, b1, nullptr, Wall, c1);           // #7
    split_tf32_kernel<<<DD * DD / 256, 256, 0, s3>>>(Wall, Wah, Wal);          // #8
    cudaEventRecord(eD, s3);

    // main: join -> fused branch-1 (aggregate + GEMM)
    cudaStreamWaitEvent(0, eB, 0);
    cudaStreamWaitEvent(0, eD, 0);
    agg_mm_tc<<<MM / 64, 256>>>(agg1h, b1i, n1i, Wah, Wal, c0, c1,
                                out + (long long)MM * DD);                     // #9
}